// round 1
// baseline (speedup 1.0000x reference)
#include <cuda_runtime.h>

#define BQ 128
#define SQ 512
#define NQ 10
#define NST 1024
#define TPB 256
#define NWARP (TPB/32)
#define PI_F 3.14159265358979f

// scratch (no allocations allowed)
__device__ float g_dta[BQ*SQ*NQ];
__device__ float g_C[BQ*SQ*NQ];

__device__ __forceinline__ float2 cmul(float2 a, float2 b){
  return make_float2(a.x*b.x - a.y*b.y, a.x*b.y + a.y*b.x);
}
// a*v + b*w (complex coefficients)
__device__ __forceinline__ float2 cmix(float2 a, float2 v, float2 b, float2 w){
  float re = a.x*v.x - a.y*v.y + b.x*w.x - b.y*w.y;
  float im = a.x*v.y + a.y*v.x + b.x*w.y + b.y*w.x;
  return make_float2(re, im);
}
// c*v + s*w (real coefficients)
__device__ __forceinline__ float2 rmix(float c, float2 v, float s, float2 w){
  return make_float2(c*v.x + s*w.x, c*v.y + s*w.y);
}

// ---------------------------------------------------------------------------
// Kernel 1: per-(b,s) preprocessing: dt_angles and C
// ---------------------------------------------------------------------------
__global__ void prep_kernel(const float* __restrict__ angles,
                            const float* __restrict__ W_x,
                            const float* __restrict__ W_dt,
                            const float* __restrict__ b_dt)
{
  int idx = blockIdx.x*blockDim.x + threadIdx.x;
  if (idx >= BQ*SQ) return;
  float a[NQ];
#pragma unroll
  for (int n=0;n<NQ;n++) a[n] = angles[idx*NQ + n];
  float dtr[5];
#pragma unroll
  for (int r=0;r<5;r++){
    float s = 0.f;
#pragma unroll
    for (int n=0;n<NQ;n++) s += a[n]*W_x[r*NQ+n];
    dtr[r]=s;
  }
#pragma unroll
  for (int k=0;k<NQ;k++){
    float s=0.f;
#pragma unroll
    for (int n=0;n<NQ;n++) s += a[n]*W_x[(15+k)*NQ+n];
    g_C[idx*NQ+k]=s;
  }
#pragma unroll
  for (int n=0;n<NQ;n++){
    float s = b_dt[n];
#pragma unroll
    for (int r=0;r<5;r++) s += dtr[r]*W_dt[n*5+r];
    // stable softplus
    float sp = fmaxf(s, 0.f) + log1pf(expf(-fabsf(s)));
    g_dta[idx*NQ+n] = tanhf(sp)*PI_F;
  }
}

// ---------------------------------------------------------------------------
// Kernel 2: the full sequential scan, one CTA per batch element.
// Wire i <-> amplitude bit (9-i)  (wire 0 is MSB of the flattened index).
// ---------------------------------------------------------------------------
__global__ __launch_bounds__(TPB, 1) void qmamba_main(
    const float* __restrict__ angles,
    const float* __restrict__ poly,
    const float* __restrict__ cparams,
    const float* __restrict__ Dg,
    float* __restrict__ out)
{
  __shared__ float2 st[2][NST];         // ping-pong state buffers
  __shared__ float  psi[NST];           // per-step RZ phase basis
  __shared__ unsigned short qperm[NST]; // QSVT CNOT-chain gather (with wrap)
  __shared__ unsigned short lperm[NST]; // layer CNOT-chain gather (no wrap)
  __shared__ float2 Ug[20][4];          // fused RZ*RY*RX 2x2 gates (2 layers x 10 wires)
  __shared__ float chs[NQ], shs[NQ], whs[NQ], fcs[NQ], fss[NQ], h_sh[NQ];
  __shared__ float pcs[4], Ds[NQ];
  __shared__ float zred[NWARP][NQ];

  const int tid = threadIdx.x;
  const int b = blockIdx.x;

  // ---- one-time tables -----------------------------------------------------
  for (int a = tid; a < NST; a += TPB) {
    // QSVT chain: CNOT(0,1)..CNOT(8,9), then CNOT(9,0). Gather applies them in
    // reverse: CNOT(c,t) -> v ^= bit(wire c) << pos(wire t); pos(w)=9-w.
    int v = a;
    v ^= (v & 1) << 9;                          // CNOT(9,0)
#pragma unroll
    for (int i = 8; i >= 0; --i) v ^= ((v >> (9-i)) & 1) << (8-i);  // CNOT(i,i+1)
    qperm[a] = (unsigned short)v;
    int u = a;                                  // layer chain: no wrap
#pragma unroll
    for (int i = 8; i >= 0; --i) u ^= ((u >> (9-i)) & 1) << (8-i);
    lperm[a] = (unsigned short)u;
  }
  if (tid < 20) {
    // U = RZ(g) * RY(b) * RX(a), applied RX first (matches reference order)
    int layer = tid/10, wire = tid%10;
    int k = (layer*NQ + wire)*3;
    float al = cparams[k], be = cparams[k+1], ga = cparams[k+2];
    float sa, ca, sb, cb, sg, cg;
    sincosf(0.5f*al, &sa, &ca);
    sincosf(0.5f*be, &sb, &cb);
    sincosf(0.5f*ga, &sg, &cg);
    // M = RY*RX
    float2 m00 = make_float2( cb*ca,  sb*sa);
    float2 m01 = make_float2(-sb*ca, -cb*sa);
    float2 m10 = make_float2( sb*ca, -cb*sa);
    float2 m11 = make_float2( cb*ca, -sb*sa);
    float2 e0 = make_float2(cg, -sg);   // e^{-i g/2}
    float2 e1 = make_float2(cg,  sg);   // e^{+i g/2}
    Ug[tid][0] = cmul(e0, m00);
    Ug[tid][1] = cmul(e0, m01);
    Ug[tid][2] = cmul(e1, m10);
    Ug[tid][3] = cmul(e1, m11);
  }
  if (tid < 4) pcs[tid] = poly[tid];
  if (tid < NQ) { Ds[tid] = Dg[tid]; h_sh[tid] = 0.f; }
  __syncthreads();

  float2* cu = st[0];
  float2* nx = st[1];

#pragma unroll 1
  for (int s = 0; s < SQ; ++s) {
    const int base_idx = (b*SQ + s)*NQ;

    // ---- per-step scalars --------------------------------------------------
    if (tid < NQ) {
      float x   = angles[base_idx + tid];
      float dta = g_dta[base_idx + tid];
      float h   = h_sh[tid];
      float s_, c_;
      sincosf(0.5f*h, &s_, &c_);
      chs[tid] = c_; shs[tid] = s_;
      whs[tid] = dta * (0.5f*PI_F);
      sincosf(0.5f*x*dta, &s_, &c_);
      fcs[tid] = c_; fss[tid] = s_;
    }
    __syncthreads();

    // hoist broadcast scalars into registers
    float rc[NQ], rs[NQ], rw[NQ];
#pragma unroll
    for (int i=0;i<NQ;i++){ rc[i]=chs[i]; rs[i]=shs[i]; rw[i]=whs[i]; }

    // ---- init product state + build Psi ------------------------------------
#pragma unroll
    for (int t = 0; t < NST/TPB; ++t) {
      int a = tid + t*TPB;
      float amp = 1.f, ps = 0.f;
#pragma unroll
      for (int i = 0; i < NQ; ++i) {
        int bit = (a >> (9-i)) & 1;
        amp *= bit ? rs[i] : rc[i];
        ps  += bit ? rw[i] : -rw[i];
      }
      cu[a]  = make_float2(amp, 0.f);
      psi[a] = ps;
    }
    __syncthreads();

    // ---- QSVT: 4x (diagonal RZ phase fused with CNOT-chain permutation) ----
#pragma unroll
    for (int d = 0; d < 4; ++d) {
      float pcd = pcs[d];
#pragma unroll
      for (int t = 0; t < NST/TPB; ++t) {
        int a = tid + t*TPB;
        int j = qperm[a];
        float2 v = cu[j];
        float phi = pcd * psi[j];
        float sp, cp;
        __sincosf(phi, &sp, &cp);
        nx[a] = make_float2(v.x*cp - v.y*sp, v.x*sp + v.y*cp);
      }
      { float2* tswap = cu; cu = nx; nx = tswap; }
      __syncthreads();
    }

    // ---- 2 variational layers: 5 fused two-wire gate passes + permutation --
#pragma unroll
    for (int L = 0; L < 2; ++L) {
#pragma unroll
      for (int jw = 0; jw < 5; ++jw) {
        const int whi = 2*jw, wlo = 2*jw+1;
        const int plo = 8 - 2*jw;          // bit of wire wlo; wire whi is plo+1
        float2 A00 = Ug[L*10+whi][0], A01 = Ug[L*10+whi][1];
        float2 A10 = Ug[L*10+whi][2], A11 = Ug[L*10+whi][3];
        float2 B00 = Ug[L*10+wlo][0], B01 = Ug[L*10+wlo][1];
        float2 B10 = Ug[L*10+wlo][2], B11 = Ug[L*10+wlo][3];
        int g = tid;                        // 256 groups of 4 amplitudes
        int bse = ((g >> plo) << (plo+2)) | (g & ((1<<plo)-1));
        int i00 = bse, i01 = bse | (1<<plo), i10 = bse | (2<<plo), i11 = bse | (3<<plo);
        float2 v00 = cu[i00], v01 = cu[i01], v10 = cu[i10], v11 = cu[i11];
        // gate A on bit plo+1 (wire whi): pairs (00,10),(01,11)
        float2 n00 = cmix(A00, v00, A01, v10);
        float2 n10 = cmix(A10, v00, A11, v10);
        float2 n01 = cmix(A00, v01, A01, v11);
        float2 n11 = cmix(A10, v01, A11, v11);
        // gate B on bit plo (wire wlo): pairs (00,01),(10,11)
        v00 = cmix(B00, n00, B01, n01);
        v01 = cmix(B10, n00, B11, n01);
        v10 = cmix(B00, n10, B01, n11);
        v11 = cmix(B10, n10, B11, n11);
        cu[i00] = v00; cu[i01] = v01; cu[i10] = v10; cu[i11] = v11;
        __syncthreads();
      }
      // CNOT chain (no wrap)
#pragma unroll
      for (int t = 0; t < NST/TPB; ++t) {
        int a = tid + t*TPB;
        nx[a] = cu[lperm[a]];
      }
      { float2* tswap = cu; cu = nx; nx = tswap; }
      __syncthreads();
    }

    // ---- final RY(x*dt): 5 fused two-wire real-gate passes -----------------
#pragma unroll
    for (int jw = 0; jw < 5; ++jw) {
      const int whi = 2*jw, wlo = 2*jw+1;
      const int plo = 8 - 2*jw;
      float cA = fcs[whi], sA = fss[whi];
      float cB = fcs[wlo], sB = fss[wlo];
      int g = tid;
      int bse = ((g >> plo) << (plo+2)) | (g & ((1<<plo)-1));
      int i00 = bse, i01 = bse | (1<<plo), i10 = bse | (2<<plo), i11 = bse | (3<<plo);
      float2 v00 = cu[i00], v01 = cu[i01], v10 = cu[i10], v11 = cu[i11];
      float2 n00 = rmix(cA, v00, -sA, v10);
      float2 n10 = rmix(sA, v00,  cA, v10);
      float2 n01 = rmix(cA, v01, -sA, v11);
      float2 n11 = rmix(sA, v01,  cA, v11);
      v00 = rmix(cB, n00, -sB, n01);
      v01 = rmix(sB, n00,  cB, n01);
      v10 = rmix(cB, n10, -sB, n11);
      v11 = rmix(sB, n10,  cB, n11);
      cu[i00] = v00; cu[i01] = v01; cu[i10] = v10; cu[i11] = v11;
      __syncthreads();
    }

    // ---- measurement: <Z_i> for all wires ----------------------------------
    float z[NQ];
#pragma unroll
    for (int i=0;i<NQ;i++) z[i] = 0.f;
#pragma unroll
    for (int t = 0; t < NST/TPB; ++t) {
      int a = tid + t*TPB;
      float2 v = cu[a];
      float p = v.x*v.x + v.y*v.y;
#pragma unroll
      for (int i=0;i<NQ;i++) z[i] += ((a >> (9-i)) & 1) ? -p : p;
    }
#pragma unroll
    for (int i=0;i<NQ;i++) {
#pragma unroll
      for (int off = 16; off > 0; off >>= 1)
        z[i] += __shfl_xor_sync(0xffffffffu, z[i], off);
    }
    const int warp = tid >> 5, lane = tid & 31;
    if (lane == 0) {
#pragma unroll
      for (int i=0;i<NQ;i++) zred[warp][i] = z[i];
    }
    __syncthreads();
    if (tid < NQ) {
      float hn = 0.f;
#pragma unroll
      for (int w = 0; w < NWARP; ++w) hn += zred[w][tid];
      h_sh[tid] = hn;
      out[base_idx + tid] = g_C[base_idx + tid]*hn + Ds[tid]*angles[base_idx + tid];
    }
    __syncthreads();
  }
}

// ---------------------------------------------------------------------------
extern "C" void kernel_launch(void* const* d_in, const int* in_sizes, int n_in,
                              void* d_out, int out_size)
{
  const float* angles  = (const float*)d_in[0];
  const float* W_x     = (const float*)d_in[1];
  const float* W_dt    = (const float*)d_in[2];
  const float* b_dt    = (const float*)d_in[3];
  const float* poly    = (const float*)d_in[4];
  const float* cparams = (const float*)d_in[5];
  const float* D       = (const float*)d_in[6];
  float* out = (float*)d_out;

  prep_kernel<<<(BQ*SQ + 255)/256, 256>>>(angles, W_x, W_dt, b_dt);
  qmamba_main<<<BQ, TPB>>>(angles, poly, cparams, D, out);
}

// round 3
// speedup vs baseline: 1.1695x; 1.1695x over previous
#include <cuda_runtime.h>

#define BQ 128
#define SQ 512
#define NQ 10
#define NST 1024
#define TPB 256
#define NWARP 8
#define PI_F 3.14159265358979f

// scratch (no allocations allowed)
__device__ float g_dta[BQ*SQ*NQ];
__device__ float g_C[BQ*SQ*NQ];

__device__ __forceinline__ float2 cmul(float2 a, float2 b){
  return make_float2(a.x*b.x - a.y*b.y, a.x*b.y + a.y*b.x);
}
__device__ __forceinline__ float2 cmix(float2 a, float2 v, float2 b, float2 w){
  float re = a.x*v.x - a.y*v.y + b.x*w.x - b.y*w.y;
  float im = a.x*v.y + a.y*v.x + b.x*w.y + b.y*w.x;
  return make_float2(re, im);
}
__device__ __forceinline__ float2 rmix(float c, float2 v, float s, float2 w){
  return make_float2(c*v.x + s*w.x, c*v.y + s*w.y);
}

// ---------------------------------------------------------------------------
__global__ void prep_kernel(const float* __restrict__ angles,
                            const float* __restrict__ W_x,
                            const float* __restrict__ W_dt,
                            const float* __restrict__ b_dt)
{
  int idx = blockIdx.x*blockDim.x + threadIdx.x;
  if (idx >= BQ*SQ) return;
  float a[NQ];
#pragma unroll
  for (int n=0;n<NQ;n++) a[n] = angles[idx*NQ + n];
  float dtr[5];
#pragma unroll
  for (int r=0;r<5;r++){
    float s = 0.f;
#pragma unroll
    for (int n=0;n<NQ;n++) s += a[n]*W_x[r*NQ+n];
    dtr[r]=s;
  }
#pragma unroll
  for (int k=0;k<NQ;k++){
    float s=0.f;
#pragma unroll
    for (int n=0;n<NQ;n++) s += a[n]*W_x[(15+k)*NQ+n];
    g_C[idx*NQ+k]=s;
  }
#pragma unroll
  for (int n=0;n<NQ;n++){
    float s = b_dt[n];
#pragma unroll
    for (int r=0;r<5;r++) s += dtr[r]*W_dt[n*5+r];
    float sp = fmaxf(s, 0.f) + log1pf(expf(-fabsf(s)));
    g_dta[idx*NQ+n] = tanhf(sp)*PI_F;
  }
}

// ---------------------------------------------------------------------------
// True-basis simulator. Wire i <-> bit (9-i).
// QSVT block (4x diag-RZ + CNOT-chain-with-wrap) folded into the init pass:
//   s4(a) = exp(i[pc3*Psi(g a) + pc2*Psi(g^2 a) + pc1*Psi(g^3 a)
//               + pc0*Psi(g^4 a)]) * s0(g^4 a)
// where g = the verified qperm gather map; T_k = g^k built by table composition.
// ---------------------------------------------------------------------------
__global__ __launch_bounds__(TPB, 1) void qmamba_main(
    const float* __restrict__ angles,
    const float* __restrict__ poly,
    const float* __restrict__ cparams,
    const float* __restrict__ Dg,
    float* __restrict__ out)
{
  __shared__ float2 st[2][NST];
  __shared__ unsigned short T1[NST], T2[NST], T3[NST], T4[NST], lp[NST];
  __shared__ float Slo[32], Shi[32], Alo[32], Ahi[32];
  __shared__ float2 Ug[20][4];
  __shared__ float chs[NQ], shs[NQ], whs[NQ], fcs[NQ], fss[NQ];
  __shared__ float pcs[4], Ds[NQ];
  __shared__ float zred[NWARP][NQ];

  const int tid = threadIdx.x;
  const int b = blockIdx.x;

  // ---- one-time tables: powers of the verified gather map --------------------
  for (int a = tid; a < NST; a += TPB) {
    int v = a;
    v ^= (v & 1) << 9;                                   // wrap CNOT(9,0) (reverse-first)
#pragma unroll
    for (int i = 8; i >= 0; --i) v ^= ((v >> (9-i)) & 1) << (8-i);
    T1[a] = (unsigned short)v;                           // g
    int u = a;
#pragma unroll
    for (int i = 8; i >= 0; --i) u ^= ((u >> (9-i)) & 1) << (8-i);
    lp[a] = (unsigned short)u;                           // layer chain gather
  }
  __syncthreads();
  for (int a = tid; a < NST; a += TPB) T2[a] = T1[T1[a]];          // g^2
  __syncthreads();
  for (int a = tid; a < NST; a += TPB) {
    T3[a] = T1[T2[a]];                                   // g^3
    T4[a] = T2[T2[a]];                                   // g^4
  }

  if (tid < 20) {
    int layer = tid/10, wire = tid%10;
    int k = (layer*NQ + wire)*3;
    float al = cparams[k], be = cparams[k+1], ga = cparams[k+2];
    float sa, ca, sb, cb, sg, cg;
    sincosf(0.5f*al, &sa, &ca);
    sincosf(0.5f*be, &sb, &cb);
    sincosf(0.5f*ga, &sg, &cg);
    float2 m00 = make_float2( cb*ca,  sb*sa);
    float2 m01 = make_float2(-sb*ca, -cb*sa);
    float2 m10 = make_float2( sb*ca, -cb*sa);
    float2 m11 = make_float2( cb*ca, -sb*sa);
    float2 e0 = make_float2(cg, -sg);
    float2 e1 = make_float2(cg,  sg);
    Ug[tid][0] = cmul(e0, m00);
    Ug[tid][1] = cmul(e0, m01);
    Ug[tid][2] = cmul(e1, m10);
    Ug[tid][3] = cmul(e1, m11);
  }
  if (tid < 4) pcs[tid] = poly[tid];
  if (tid < NQ) {
    Ds[tid] = Dg[tid];
    // step-0 scalars (h = 0)
    int bi = (b*SQ)*NQ + tid;
    float x = angles[bi], dta = g_dta[bi];
    chs[tid] = 1.f; shs[tid] = 0.f;
    whs[tid] = dta * (0.5f*PI_F);
    float s_, c_;
    __sincosf(0.5f*x*dta, &s_, &c_);
    fcs[tid] = c_; fss[tid] = s_;
  }
  __syncthreads();

  float2* cu = st[0];
  float2* nx = st[1];

  // ---- sequential scan -------------------------------------------------------
#pragma unroll 1
  for (int s = 0; s < SQ; ++s) {
    // per-step split tables over 5-bit halves: psi weights + product amplitudes
    if (tid < 64) {
      int j = tid & 31;
      bool hi = tid >= 32;
      float sm = 0.f, am = 1.f;
#pragma unroll
      for (int q=0;q<5;q++){
        int w = hi ? (4-q) : (9-q);   // bit (5+q) <-> wire 4-q ; bit q <-> wire 9-q
        int bit = (j>>q)&1;
        sm += bit ? whs[w] : -whs[w];
        am *= bit ? shs[w] : chs[w];
      }
      if (hi){ Shi[j]=sm; Ahi[j]=am; } else { Slo[j]=sm; Alo[j]=am; }
    }
    __syncthreads();

    // init pass: product state advanced through the entire QSVT block
    {
      float p0=pcs[0], p1=pcs[1], p2=pcs[2], p3=pcs[3];
      int basea = tid<<2;
#pragma unroll
      for (int k=0;k<4;k++){
        int a = basea+k;
        int m1=T1[a], m2=T2[a], m3=T3[a], m4=T4[a];
        float phi = p3*(Shi[m1>>5] + Slo[m1&31])
                  + p2*(Shi[m2>>5] + Slo[m2&31])
                  + p1*(Shi[m3>>5] + Slo[m3&31])
                  + p0*(Shi[m4>>5] + Slo[m4&31]);
        float amp = Ahi[m4>>5] * Alo[m4&31];
        float sp, cp; __sincosf(phi, &sp, &cp);
        cu[a] = make_float2(amp*cp, amp*sp);
      }
    }
    __syncthreads();

    // ---- 2 variational layers: 5 two-wire gate passes + chain gather --------
#pragma unroll
    for (int L = 0; L < 2; ++L) {
#pragma unroll
      for (int jw = 0; jw < 5; ++jw) {
        const int whi = 2*jw;
        const int plo = 8 - 2*jw;
        float2 A00 = Ug[L*10+whi][0], A01 = Ug[L*10+whi][1];
        float2 A10 = Ug[L*10+whi][2], A11 = Ug[L*10+whi][3];
        float2 B00 = Ug[L*10+whi+1][0], B01 = Ug[L*10+whi+1][1];
        float2 B10 = Ug[L*10+whi+1][2], B11 = Ug[L*10+whi+1][3];
        int g = tid;
        int bse = ((g >> plo) << (plo+2)) | (g & ((1<<plo)-1));
        int i00 = bse, i01 = bse | (1<<plo), i10 = bse | (2<<plo), i11 = bse | (3<<plo);
        float2 v00 = cu[i00], v01 = cu[i01], v10 = cu[i10], v11 = cu[i11];
        float2 n00 = cmix(A00, v00, A01, v10);
        float2 n10 = cmix(A10, v00, A11, v10);
        float2 n01 = cmix(A00, v01, A01, v11);
        float2 n11 = cmix(A10, v01, A11, v11);
        v00 = cmix(B00, n00, B01, n01);
        v01 = cmix(B10, n00, B11, n01);
        v10 = cmix(B00, n10, B01, n11);
        v11 = cmix(B10, n10, B11, n11);
        cu[i00] = v00; cu[i01] = v01; cu[i10] = v10; cu[i11] = v11;
        __syncthreads();
      }
#pragma unroll
      for (int t = 0; t < NST/TPB; ++t) {
        int a = tid + t*TPB;
        nx[a] = cu[lp[a]];
      }
      { float2* tswap = cu; cu = nx; nx = tswap; }
      __syncthreads();
    }

    // ---- final RY(x*dt): 5 two-wire real passes; measurement fused in last --
    float z[NQ];
#pragma unroll
    for (int i=0;i<NQ;i++) z[i] = 0.f;
#pragma unroll
    for (int jw = 0; jw < 5; ++jw) {
      const int plo = 8 - 2*jw;
      float cA = fcs[2*jw], sA = fss[2*jw];
      float cB = fcs[2*jw+1], sB = fss[2*jw+1];
      int g = tid;
      int bse = ((g >> plo) << (plo+2)) | (g & ((1<<plo)-1));
      int i00 = bse, i01 = bse | (1<<plo), i10 = bse | (2<<plo), i11 = bse | (3<<plo);
      float2 v00 = cu[i00], v01 = cu[i01], v10 = cu[i10], v11 = cu[i11];
      float2 n00 = rmix(cA, v00, -sA, v10);
      float2 n10 = rmix(sA, v00,  cA, v10);
      float2 n01 = rmix(cA, v01, -sA, v11);
      float2 n11 = rmix(sA, v01,  cA, v11);
      v00 = rmix(cB, n00, -sB, n01);
      v01 = rmix(sB, n00,  cB, n01);
      v10 = rmix(cB, n10, -sB, n11);
      v11 = rmix(sB, n10,  cB, n11);
      if (jw < 4) {
        cu[i00] = v00; cu[i01] = v01; cu[i10] = v10; cu[i11] = v11;
        __syncthreads();
      } else {
        // plo==0: quad = consecutive indices 4*tid .. 4*tid+3
        int   idx[4] = {i00, i01, i10, i11};
        float2 vv[4] = {v00, v01, v10, v11};
#pragma unroll
        for (int m=0;m<4;m++){
          float p = vv[m].x*vv[m].x + vv[m].y*vv[m].y;
          int a = idx[m];
#pragma unroll
          for (int i=0;i<NQ;i++) z[i] += ((a >> (9-i)) & 1) ? -p : p;
        }
      }
    }

    // ---- reduce <Z_i>, h update, output -------------------------------------
#pragma unroll
    for (int i=0;i<NQ;i++){
#pragma unroll
      for (int off=16; off>0; off>>=1)
        z[i] += __shfl_xor_sync(0xffffffffu, z[i], off);
    }
    const int warp = tid>>5, lane = tid&31;
    if (lane == 0){
#pragma unroll
      for (int i=0;i<NQ;i++) zred[warp][i] = z[i];
    }
    __syncthreads();
    if (tid < NQ){
      float hn = 0.f;
#pragma unroll
      for (int w=0; w<NWARP; ++w) hn += zred[w][tid];
      int bi = (b*SQ+s)*NQ + tid;
      out[bi] = g_C[bi]*hn + Ds[tid]*angles[bi];
      if (s+1 < SQ){
        int bn = bi + NQ;
        float x = angles[bn], dta = g_dta[bn];
        float s_, c_;
        __sincosf(0.5f*hn, &s_, &c_);
        chs[tid] = c_; shs[tid] = s_;
        whs[tid] = dta * (0.5f*PI_F);
        __sincosf(0.5f*x*dta, &s_, &c_);
        fcs[tid] = c_; fss[tid] = s_;
      }
    }
    __syncthreads();
  }
}

// ---------------------------------------------------------------------------
extern "C" void kernel_launch(void* const* d_in, const int* in_sizes, int n_in,
                              void* d_out, int out_size)
{
  const float* angles  = (const float*)d_in[0];
  const float* W_x     = (const float*)d_in[1];
  const float* W_dt    = (const float*)d_in[2];
  const float* b_dt    = (const float*)d_in[3];
  const float* poly    = (const float*)d_in[4];
  const float* cparams = (const float*)d_in[5];
  const float* D       = (const float*)d_in[6];
  float* out = (float*)d_out;

  prep_kernel<<<(BQ*SQ + 255)/256, 256>>>(angles, W_x, W_dt, b_dt);
  qmamba_main<<<BQ, TPB>>>(angles, poly, cparams, D, out);
}

// round 4
// speedup vs baseline: 1.3251x; 1.1331x over previous
#include <cuda_runtime.h>

#define BQ 128
#define SQ 512
#define NQ 10
#define NST 1024
#define TPB 128
#define AMPS 8
#define PI_F 3.14159265358979f

// scratch (no allocations allowed)
__device__ float g_dta[BQ*SQ*NQ];
__device__ float g_C[BQ*SQ*NQ];

__device__ __forceinline__ float2 cmul(float2 a, float2 b){
  return make_float2(a.x*b.x - a.y*b.y, a.x*b.y + a.y*b.x);
}
__device__ __forceinline__ float2 cmix(float2 a, float2 v, float2 b, float2 w){
  float re = a.x*v.x - a.y*v.y + b.x*w.x - b.y*w.y;
  float im = a.x*v.y + a.y*v.x + b.x*w.y + b.y*w.x;
  return make_float2(re, im);
}

// verified QSVT gather map (round 3): wrap CNOT(9,0) then chain, reverse-applied
__device__ __forceinline__ int gmap(int a){
  int v = a;
  v ^= (v & 1) << 9;
#pragma unroll
  for (int i = 8; i >= 0; --i) v ^= ((v >> (9-i)) & 1) << (8-i);
  return v;
}

// ---------------------------------------------------------------------------
__global__ void prep_kernel(const float* __restrict__ angles,
                            const float* __restrict__ W_x,
                            const float* __restrict__ W_dt,
                            const float* __restrict__ b_dt)
{
  int idx = blockIdx.x*blockDim.x + threadIdx.x;
  if (idx >= BQ*SQ) return;
  float a[NQ];
#pragma unroll
  for (int n=0;n<NQ;n++) a[n] = angles[idx*NQ + n];
  float dtr[5];
#pragma unroll
  for (int r=0;r<5;r++){
    float s = 0.f;
#pragma unroll
    for (int n=0;n<NQ;n++) s += a[n]*W_x[r*NQ+n];
    dtr[r]=s;
  }
#pragma unroll
  for (int k=0;k<NQ;k++){
    float s=0.f;
#pragma unroll
    for (int n=0;n<NQ;n++) s += a[n]*W_x[(15+k)*NQ+n];
    g_C[idx*NQ+k]=s;
  }
#pragma unroll
  for (int n=0;n<NQ;n++){
    float s = b_dt[n];
#pragma unroll
    for (int r=0;r<5;r++) s += dtr[r]*W_dt[n*5+r];
    float sp = fmaxf(s, 0.f) + log1pf(expf(-fabsf(s)));
    g_dta[idx*NQ+n] = tanhf(sp)*PI_F;
  }
}

// complex shuffle gate on lane bit q
__device__ __forceinline__ void shflC(float2* v, const float2* G, int q, int lane){
  int bt = (lane >> q) & 1;
  float2 g0=G[0], g1=G[1], g2=G[2], g3=G[3];
  float2 cs = bt ? g3 : g0;
  float2 cp = bt ? g2 : g1;
#pragma unroll
  for (int m=0;m<AMPS;m++){
    float px = __shfl_xor_sync(0xffffffffu, v[m].x, 1<<q);
    float py = __shfl_xor_sync(0xffffffffu, v[m].y, 1<<q);
    float nx = cs.x*v[m].x - cs.y*v[m].y + cp.x*px - cp.y*py;
    float ny = cs.x*v[m].y + cs.y*v[m].x + cp.x*py + cp.y*px;
    v[m] = make_float2(nx, ny);
  }
}

// real (RY) shuffle gate on lane bit q
__device__ __forceinline__ void shflR(float2* v, float c, float s, int q, int lane){
  int bt = (lane >> q) & 1;
  float sp = bt ? s : -s;   // new = c*v + sp*partner
#pragma unroll
  for (int m=0;m<AMPS;m++){
    float px = __shfl_xor_sync(0xffffffffu, v[m].x, 1<<q);
    float py = __shfl_xor_sync(0xffffffffu, v[m].y, 1<<q);
    v[m] = make_float2(c*v[m].x + sp*px, c*v[m].y + sp*py);
  }
}

// complex register gate on m-bit bm
__device__ __forceinline__ void regC(float2* v, const float2* G, int bm){
  float2 g0=G[0], g1=G[1], g2=G[2], g3=G[3];
#pragma unroll
  for (int m=0;m<AMPS;m++){
    if (m & bm) continue;
    int mh = m | bm;
    float2 lo = v[m], hi = v[mh];
    v[m]  = cmix(g0, lo, g1, hi);
    v[mh] = cmix(g2, lo, g3, hi);
  }
}

// real (RY) register gate on m-bit bm
__device__ __forceinline__ void regR(float2* v, float c, float s, int bm){
#pragma unroll
  for (int m=0;m<AMPS;m++){
    if (m & bm) continue;
    int mh = m | bm;
    float2 lo = v[m], hi = v[mh];
    v[m]  = make_float2(c*lo.x - s*hi.x, c*lo.y - s*hi.y);
    v[mh] = make_float2(s*lo.x + c*hi.x, s*lo.y + c*hi.y);
  }
}

// ---------------------------------------------------------------------------
// 128 threads, 8 amps/thread. amp a = tid*8+m. bits: [2:0]=m, [7:3]=lane, [9:8]=warp.
// wire w <-> bit (9-w). wires 0,1 = warp bits (shared rounds, chain gather fused);
// wires 2..6 = lane bits (shuffles); wires 7,8,9 = reg bits.
// pos(a) = (a&7)*128 + (a>>3)   (SoA-by-m buffer layout; conflict-free writes)
// ---------------------------------------------------------------------------
__global__ __launch_bounds__(TPB, 1) void qmamba_main(
    const float* __restrict__ angles,
    const float* __restrict__ poly,
    const float* __restrict__ cparams,
    const float* __restrict__ Dg,
    float* __restrict__ out)
{
  __shared__ float2 bufA[NST], bufB[NST];
  __shared__ float2 Ug[20][4];
  __shared__ float Slo[32], Shi[32], Alo[32], Ahi[32];
  __shared__ float chs[NQ], shs[NQ], whs[NQ], fcs[NQ], fss[NQ];
  __shared__ float pcs[4], Dsh[NQ];
  __shared__ float zred[4][NQ];

  const int tid = threadIdx.x;
  const int lane = tid & 31;
  const int b = blockIdx.x;

  // ---- setup ---------------------------------------------------------------
  if (tid < 20) {
    int layer = tid/10, wire = tid%10;
    int k = (layer*NQ + wire)*3;
    float al = cparams[k], be = cparams[k+1], ga = cparams[k+2];
    float sa, ca, sb, cb, sg, cg;
    sincosf(0.5f*al, &sa, &ca);
    sincosf(0.5f*be, &sb, &cb);
    sincosf(0.5f*ga, &sg, &cg);
    float2 m00 = make_float2( cb*ca,  sb*sa);
    float2 m01 = make_float2(-sb*ca, -cb*sa);
    float2 m10 = make_float2( sb*ca, -cb*sa);
    float2 m11 = make_float2( cb*ca, -sb*sa);
    float2 e0 = make_float2(cg, -sg);
    float2 e1 = make_float2(cg,  sg);
    Ug[tid][0] = cmul(e0, m00);
    Ug[tid][1] = cmul(e0, m01);
    Ug[tid][2] = cmul(e1, m10);
    Ug[tid][3] = cmul(e1, m11);
  }
  if (tid < 4) pcs[tid] = poly[tid];
  float pA = 0.f, pC = 0.f;   // carried per-step inputs (tid<10 only)
  if (tid < NQ) {
    Dsh[tid] = Dg[tid];
    int bi = b*SQ*NQ + tid;
    pA = angles[bi]; pC = g_C[bi];
    float dta = g_dta[bi];
    chs[tid] = 1.f; shs[tid] = 0.f;   // h = 0 at step 0
    whs[tid] = dta * (0.5f*PI_F);
    float s_, c_;
    __sincosf(0.5f*pA*dta, &s_, &c_);
    fcs[tid] = c_; fss[tid] = s_;
  }
  __syncthreads();

  // per-thread static: QSVT gather powers + fused-gather positions
  int rT1[AMPS], rT2[AMPS], rT3[AMPS], rT4[AMPS], posJ[AMPS];
#pragma unroll
  for (int m=0;m<AMPS;m++){
    int a = tid*AMPS + m;
    rT1[m] = gmap(a);
    rT2[m] = gmap(rT1[m]);
    rT3[m] = gmap(rT2[m]);
    rT4[m] = gmap(rT3[m]);
    int j0 = a ^ (a >> 1);                 // layer CNOT-chain gather (linear)
    posJ[m] = ((j0 & 7) << 7) | (j0 >> 3);
  }

  // cross-round combined 2-wire coefficients (wires 0,1), per thread
  const int r1 = (tid >> 6) & 1;   // amp bit 9
  const int r0 = (tid >> 5) & 1;   // amp bit 8
  float2 K1[4], K2[4];
#pragma unroll
  for (int d=0; d<4; d++){
    int d1 = (d>>1)&1, d0 = d&1;
    K1[d] = cmul(Ug[0 ][r1*2 + (r1^d1)], Ug[1 ][r0*2 + (r0^d0)]);
    K2[d] = cmul(Ug[10][r1*2 + (r1^d1)], Ug[11][r0*2 + (r0^d0)]);
  }

  float2 v[AMPS];

  // ---- sequential scan -----------------------------------------------------
#pragma unroll 1
  for (int s = 0; s < SQ; ++s) {
    // prefetch next-step per-wire inputs (latency hidden by whole step body)
    float nA=0.f, nD=0.f, nC=0.f;
    if (tid < NQ && s+1 < SQ) {
      int bn = (b*SQ + s + 1)*NQ + tid;
      nA = angles[bn]; nD = g_dta[bn]; nC = g_C[bn];
    }
    // per-step split tables over 5-bit halves
    if (tid < 64) {
      int j = tid & 31;
      bool hi = tid >= 32;
      float sm = 0.f, am = 1.f;
#pragma unroll
      for (int q=0;q<5;q++){
        int w = hi ? (4-q) : (9-q);
        int bit = (j>>q)&1;
        sm += bit ? whs[w] : -whs[w];
        am *= bit ? shs[w] : chs[w];
      }
      if (hi){ Shi[j]=sm; Ahi[j]=am; } else { Slo[j]=sm; Alo[j]=am; }
    }
    __syncthreads();

    // init in registers: product state advanced through entire QSVT block
    {
      float p0=pcs[0], p1=pcs[1], p2=pcs[2], p3=pcs[3];
#pragma unroll
      for (int m=0;m<AMPS;m++){
        float phi = p3*(Shi[rT1[m]>>5] + Slo[rT1[m]&31])
                  + p2*(Shi[rT2[m]>>5] + Slo[rT2[m]&31])
                  + p1*(Shi[rT3[m]>>5] + Slo[rT3[m]&31])
                  + p0*(Shi[rT4[m]>>5] + Slo[rT4[m]&31]);
        float am = Ahi[rT4[m]>>5] * Alo[rT4[m]&31];
        float sp, cp; __sincosf(phi, &sp, &cp);
        v[m] = make_float2(am*cp, am*sp);
      }
    }

    // ======== section 1: layer-1 gates ========
    // cross 2-wire gate (wires 0,1) — shared round, no gather
#pragma unroll
    for (int m=0;m<AMPS;m++) bufA[m*TPB + tid] = v[m];
    __syncthreads();
#pragma unroll
    for (int m=0;m<AMPS;m++){
      int p = m*TPB + tid;   // pos(a)
      float2 w0 = bufA[p], w1 = bufA[p^32], w2 = bufA[p^64], w3 = bufA[p^96];
      float2 r = cmix(K1[0], w0, K1[1], w1);
      v[m] = cmix(make_float2(1.f,0.f), r, K1[2], w2);   // r + K1[2]*w2
      v[m].x += K1[3].x*w3.x - K1[3].y*w3.y;
      v[m].y += K1[3].x*w3.y + K1[3].y*w3.x;
    }
    shflC(v, Ug[2], 4, lane);
    shflC(v, Ug[3], 3, lane);
    shflC(v, Ug[4], 2, lane);
    shflC(v, Ug[5], 1, lane);
    shflC(v, Ug[6], 0, lane);
    regC(v, Ug[7], 4);
    regC(v, Ug[8], 2);
    regC(v, Ug[9], 1);

    // ======== section 2: chain gather fused with layer-2 cross gate ========
#pragma unroll
    for (int m=0;m<AMPS;m++) bufB[m*TPB + tid] = v[m];
    __syncthreads();
#pragma unroll
    for (int m=0;m<AMPS;m++){
      int p = posJ[m];
      float2 w0 = bufB[p], w1 = bufB[p^0x30], w2 = bufB[p^0x60], w3 = bufB[p^0x50];
      float2 r = cmix(K2[0], w0, K2[1], w1);
      r.x += K2[2].x*w2.x - K2[2].y*w2.y + K2[3].x*w3.x - K2[3].y*w3.y;
      r.y += K2[2].x*w2.y + K2[2].y*w2.x + K2[3].x*w3.y + K2[3].y*w3.x;
      v[m] = r;
    }
    shflC(v, Ug[12], 4, lane);
    shflC(v, Ug[13], 3, lane);
    shflC(v, Ug[14], 2, lane);
    shflC(v, Ug[15], 1, lane);
    shflC(v, Ug[16], 0, lane);
    regC(v, Ug[17], 4);
    regC(v, Ug[18], 2);
    regC(v, Ug[19], 1);

    // ======== section 3: chain gather fused with final-RY cross gate ========
    {
      float cA = fcs[0], sA = fss[0], cB = fcs[1], sB = fss[1];
      float tA1 = r1 ? sA : -sA;
      float tB1 = r0 ? sB : -sB;
      float K30 = cA*cB, K31 = cA*tB1, K32 = tA1*cB, K33 = tA1*tB1;
#pragma unroll
      for (int m=0;m<AMPS;m++) bufA[m*TPB + tid] = v[m];
      __syncthreads();
#pragma unroll
      for (int m=0;m<AMPS;m++){
        int p = posJ[m];
        float2 w0 = bufA[p], w1 = bufA[p^0x30], w2 = bufA[p^0x60], w3 = bufA[p^0x50];
        v[m].x = K30*w0.x + K31*w1.x + K32*w2.x + K33*w3.x;
        v[m].y = K30*w0.y + K31*w1.y + K32*w2.y + K33*w3.y;
      }
    }
    shflR(v, fcs[2], fss[2], 4, lane);
    shflR(v, fcs[3], fss[3], 3, lane);
    shflR(v, fcs[4], fss[4], 2, lane);
    shflR(v, fcs[5], fss[5], 1, lane);
    shflR(v, fcs[6], fss[6], 0, lane);
    regR(v, fcs[7], fss[7], 4);
    regR(v, fcs[8], fss[8], 2);
    regR(v, fcs[9], fss[9], 1);

    // ======== measurement ========
    float S=0.f, Sb0=0.f, Sb1=0.f, Sb2=0.f;
#pragma unroll
    for (int m=0;m<AMPS;m++){
      float pm = v[m].x*v[m].x + v[m].y*v[m].y;
      S += pm;
      if (m & 1) Sb0 += pm;
      if (m & 2) Sb1 += pm;
      if (m & 4) Sb2 += pm;
    }
    float z[NQ];
#pragma unroll
    for (int i=0;i<7;i++) z[i] = ((tid >> (6-i)) & 1) ? -S : S;
    z[7] = S - 2.f*Sb2;
    z[8] = S - 2.f*Sb1;
    z[9] = S - 2.f*Sb0;
#pragma unroll
    for (int i=0;i<NQ;i++){
#pragma unroll
      for (int off=16; off>0; off>>=1)
        z[i] += __shfl_xor_sync(0xffffffffu, z[i], off);
    }
    if (lane == 0){
      int w = tid >> 5;
#pragma unroll
      for (int i=0;i<NQ;i++) zred[w][i] = z[i];
    }
    __syncthreads();
    if (tid < NQ){
      float hn = zred[0][tid] + zred[1][tid] + zred[2][tid] + zred[3][tid];
      int bi = (b*SQ + s)*NQ + tid;
      out[bi] = pC*hn + Dsh[tid]*pA;
      if (s+1 < SQ){
        float s_, c_;
        __sincosf(0.5f*hn, &s_, &c_);
        chs[tid] = c_; shs[tid] = s_;
        whs[tid] = nD * (0.5f*PI_F);
        __sincosf(0.5f*nA*nD, &s_, &c_);
        fcs[tid] = c_; fss[tid] = s_;
        pA = nA; pC = nC;
      }
    }
    __syncthreads();
  }
}

// ---------------------------------------------------------------------------
extern "C" void kernel_launch(void* const* d_in, const int* in_sizes, int n_in,
                              void* d_out, int out_size)
{
  const float* angles  = (const float*)d_in[0];
  const float* W_x     = (const float*)d_in[1];
  const float* W_dt    = (const float*)d_in[2];
  const float* b_dt    = (const float*)d_in[3];
  const float* poly    = (const float*)d_in[4];
  const float* cparams = (const float*)d_in[5];
  const float* D       = (const float*)d_in[6];
  float* out = (float*)d_out;

  prep_kernel<<<(BQ*SQ + 255)/256, 256>>>(angles, W_x, W_dt, b_dt);
  qmamba_main<<<BQ, TPB>>>(angles, poly, cparams, D, out);
}

// round 5
// speedup vs baseline: 1.6870x; 1.2731x over previous
#include <cuda_runtime.h>

#define BQ 128
#define SQ 512
#define NQ 10
#define NST 1024
#define TPB 256
#define AMPS 4
#define PI_F 3.14159265358979f

// scratch (no allocations allowed)
__device__ float g_dta[BQ*SQ*NQ];
__device__ float g_C[BQ*SQ*NQ];

__device__ __forceinline__ float2 cmul(float2 a, float2 b){
  return make_float2(a.x*b.x - a.y*b.y, a.x*b.y + a.y*b.x);
}
__device__ __forceinline__ float2 cmix(float2 a, float2 v, float2 b, float2 w){
  float re = a.x*v.x - a.y*v.y + b.x*w.x - b.y*w.y;
  float im = a.x*v.y + a.y*v.x + b.x*w.y + b.y*w.x;
  return make_float2(re, im);
}

// verified QSVT gather map: wrap CNOT(9,0) then chain, reverse-applied
__device__ __forceinline__ int gmap(int a){
  int v = a;
  v ^= (v & 1) << 9;
#pragma unroll
  for (int i = 8; i >= 0; --i) v ^= ((v >> (9-i)) & 1) << (8-i);
  return v;
}

// ---------------------------------------------------------------------------
__global__ void prep_kernel(const float* __restrict__ angles,
                            const float* __restrict__ W_x,
                            const float* __restrict__ W_dt,
                            const float* __restrict__ b_dt)
{
  int idx = blockIdx.x*blockDim.x + threadIdx.x;
  if (idx >= BQ*SQ) return;
  float a[NQ];
#pragma unroll
  for (int n=0;n<NQ;n++) a[n] = angles[idx*NQ + n];
  float dtr[5];
#pragma unroll
  for (int r=0;r<5;r++){
    float s = 0.f;
#pragma unroll
    for (int n=0;n<NQ;n++) s += a[n]*W_x[r*NQ+n];
    dtr[r]=s;
  }
#pragma unroll
  for (int k=0;k<NQ;k++){
    float s=0.f;
#pragma unroll
    for (int n=0;n<NQ;n++) s += a[n]*W_x[(15+k)*NQ+n];
    g_C[idx*NQ+k]=s;
  }
#pragma unroll
  for (int n=0;n<NQ;n++){
    float s = b_dt[n];
#pragma unroll
    for (int r=0;r<5;r++) s += dtr[r]*W_dt[n*5+r];
    float sp = fmaxf(s, 0.f) + log1pf(expf(-fabsf(s)));
    g_dta[idx*NQ+n] = tanhf(sp)*PI_F;
  }
}

// complex shuffle gate on lane bit q
__device__ __forceinline__ void shflC(float2* v, const float2* G, int q, int lane){
  int bt = (lane >> q) & 1;
  float2 g0=G[0], g1=G[1], g2=G[2], g3=G[3];
  float2 cs = bt ? g3 : g0;
  float2 cp = bt ? g2 : g1;
#pragma unroll
  for (int m=0;m<AMPS;m++){
    float px = __shfl_xor_sync(0xffffffffu, v[m].x, 1<<q);
    float py = __shfl_xor_sync(0xffffffffu, v[m].y, 1<<q);
    float nx = cs.x*v[m].x - cs.y*v[m].y + cp.x*px - cp.y*py;
    float ny = cs.x*v[m].y + cs.y*v[m].x + cp.x*py + cp.y*px;
    v[m] = make_float2(nx, ny);
  }
}

// real (RY) shuffle gate on lane bit q
__device__ __forceinline__ void shflR(float2* v, float c, float s, int q, int lane){
  int bt = (lane >> q) & 1;
  float sp = bt ? s : -s;
#pragma unroll
  for (int m=0;m<AMPS;m++){
    float px = __shfl_xor_sync(0xffffffffu, v[m].x, 1<<q);
    float py = __shfl_xor_sync(0xffffffffu, v[m].y, 1<<q);
    v[m] = make_float2(c*v[m].x + sp*px, c*v[m].y + sp*py);
  }
}

// complex register gate on m-bit bm
__device__ __forceinline__ void regC(float2* v, const float2* G, int bm){
  float2 g0=G[0], g1=G[1], g2=G[2], g3=G[3];
#pragma unroll
  for (int m=0;m<AMPS;m++){
    if (m & bm) continue;
    int mh = m | bm;
    float2 lo = v[m], hi = v[mh];
    v[m]  = cmix(g0, lo, g1, hi);
    v[mh] = cmix(g2, lo, g3, hi);
  }
}

// real (RY) register gate on m-bit bm
__device__ __forceinline__ void regR(float2* v, float c, float s, int bm){
#pragma unroll
  for (int m=0;m<AMPS;m++){
    if (m & bm) continue;
    int mh = m | bm;
    float2 lo = v[m], hi = v[mh];
    v[m]  = make_float2(c*lo.x - s*hi.x, c*lo.y - s*hi.y);
    v[mh] = make_float2(s*lo.x + c*hi.x, s*lo.y + c*hi.y);
  }
}

// ---------------------------------------------------------------------------
// 256 threads, 4 amps/thread. amp a = tid*4+m.
// bits: [1:0]=m (wires 8,9), [6:2]=lane (wires 3..7), [9:7]=warp (wires 0,1,2).
// pos(a) = (a&3)*256 + (a>>2). Cross round = 8-way combine over warp bits with
// per-warp coefficient products Ksh (LDS broadcast). Chain gather fused into
// cross-round read addresses via masks (d<<5)^(d<<4).
// ---------------------------------------------------------------------------
__global__ __launch_bounds__(TPB, 1) void qmamba_main(
    const float* __restrict__ angles,
    const float* __restrict__ poly,
    const float* __restrict__ cparams,
    const float* __restrict__ Dg,
    float* __restrict__ out)
{
  __shared__ float2 bufA[NST], bufB[NST];
  __shared__ float2 Ug[20][4];
  __shared__ float2 Ksh[2][8][8];     // static cross-coeffs per layer/warp/d
  __shared__ float2 K3sh[8][8];       // per-step RY cross-coeffs (real in .x/.y? no: stored as float2 with .y=0 unused) 
  __shared__ float Slo[32], Shi[32], Alo[32], Ahi[32];
  __shared__ float chs[NQ], shs[NQ], whs[NQ], fcs[NQ], fss[NQ];
  __shared__ float pcs[4], Dsh[NQ];
  __shared__ float zred[8][NQ];

  const int tid = threadIdx.x;
  const int lane = tid & 31;
  const int warp = tid >> 5;
  const int b = blockIdx.x;

  // ---- setup ---------------------------------------------------------------
  if (tid < 20) {
    int layer = tid/10, wire = tid%10;
    int k = (layer*NQ + wire)*3;
    float al = cparams[k], be = cparams[k+1], ga = cparams[k+2];
    float sa, ca, sb, cb, sg, cg;
    sincosf(0.5f*al, &sa, &ca);
    sincosf(0.5f*be, &sb, &cb);
    sincosf(0.5f*ga, &sg, &cg);
    float2 m00 = make_float2( cb*ca,  sb*sa);
    float2 m01 = make_float2(-sb*ca, -cb*sa);
    float2 m10 = make_float2( sb*ca, -cb*sa);
    float2 m11 = make_float2( cb*ca, -sb*sa);
    float2 e0 = make_float2(cg, -sg);
    float2 e1 = make_float2(cg,  sg);
    Ug[tid][0] = cmul(e0, m00);
    Ug[tid][1] = cmul(e0, m01);
    Ug[tid][2] = cmul(e1, m10);
    Ug[tid][3] = cmul(e1, m11);
  }
  if (tid < 4) pcs[tid] = poly[tid];
  float pA = 0.f, pC = 0.f;
  if (tid < NQ) {
    Dsh[tid] = Dg[tid];
    int bi = b*SQ*NQ + tid;
    pA = angles[bi]; pC = g_C[bi];
    float dta = g_dta[bi];
    chs[tid] = 1.f; shs[tid] = 0.f;     // h=0 at step 0
    whs[tid] = dta * (0.5f*PI_F);
    float s_, c_;
    __sincosf(0.5f*pA*dta, &s_, &c_);
    fcs[tid] = c_; fss[tid] = s_;
  }
  __syncthreads();

  // static cross coefficients: K[L][w][d] = Ug[L*10+0..2] tensor products
  if (tid < 128) {
    int L = tid >> 6, w = (tid >> 3) & 7, d = tid & 7;
    int rA = (w>>2)&1, rB = (w>>1)&1, rC = w&1;
    int dA = (d>>2)&1, dB = (d>>1)&1, dC = d&1;
    float2 k = cmul(Ug[L*10+0][rA*2 + (rA^dA)],
               cmul(Ug[L*10+1][rB*2 + (rB^dB)],
                    Ug[L*10+2][rC*2 + (rC^dC)]));
    Ksh[L][w][d] = k;
  }

  // per-thread static: QSVT gather powers + fused-gather positions
  int rT1[AMPS], rT2[AMPS], rT3[AMPS], rT4[AMPS], posJ[AMPS];
#pragma unroll
  for (int m=0;m<AMPS;m++){
    int a = tid*AMPS + m;
    rT1[m] = gmap(a);
    rT2[m] = gmap(rT1[m]);
    rT3[m] = gmap(rT2[m]);
    rT4[m] = gmap(rT3[m]);
    int j0 = a ^ (a >> 1);
    posJ[m] = ((j0 & 3) << 8) | (j0 >> 2);
  }
  __syncthreads();

  float2 v[AMPS];

  // ---- sequential scan -----------------------------------------------------
#pragma unroll 1
  for (int s = 0; s < SQ; ++s) {
    // prefetch next-step per-wire inputs
    float nA=0.f, nD=0.f, nC=0.f;
    if (tid < NQ && s+1 < SQ) {
      int bn = (b*SQ + s + 1)*NQ + tid;
      nA = angles[bn]; nD = g_dta[bn]; nC = g_C[bn];
    }
    // per-step split tables over 5-bit halves
    if (tid < 64) {
      int j = tid & 31;
      bool hi = tid >= 32;
      float sm = 0.f, am = 1.f;
#pragma unroll
      for (int q=0;q<5;q++){
        int w = hi ? (4-q) : (9-q);
        int bit = (j>>q)&1;
        sm += bit ? whs[w] : -whs[w];
        am *= bit ? shs[w] : chs[w];
      }
      if (hi){ Shi[j]=sm; Ahi[j]=am; } else { Slo[j]=sm; Alo[j]=am; }
    }
    // per-step final-RY cross coefficients (wires 0,1,2), per warp/d
    if (tid >= 64 && tid < 128) {
      int t = tid - 64;
      int w = t >> 3, d = t & 7;
      float f0 = (d&4) ? ((w&4) ? fss[0] : -fss[0]) : fcs[0];
      float f1 = (d&2) ? ((w&2) ? fss[1] : -fss[1]) : fcs[1];
      float f2 = (d&1) ? ((w&1) ? fss[2] : -fss[2]) : fcs[2];
      K3sh[w][d] = make_float2(f0*f1*f2, 0.f);
    }
    __syncthreads();

    // init in registers: product state advanced through entire QSVT block
    {
      float p0=pcs[0], p1=pcs[1], p2=pcs[2], p3=pcs[3];
#pragma unroll
      for (int m=0;m<AMPS;m++){
        float phi = p3*(Shi[rT1[m]>>5] + Slo[rT1[m]&31])
                  + p2*(Shi[rT2[m]>>5] + Slo[rT2[m]&31])
                  + p1*(Shi[rT3[m]>>5] + Slo[rT3[m]&31])
                  + p0*(Shi[rT4[m]>>5] + Slo[rT4[m]&31]);
        float am = Ahi[rT4[m]>>5] * Alo[rT4[m]&31];
        float sp, cp; __sincosf(phi, &sp, &cp);
        v[m] = make_float2(am*cp, am*sp);
      }
    }

    // ======== section 1: layer-1 gates ========
#pragma unroll
    for (int m=0;m<AMPS;m++) bufA[(m<<8) + tid] = v[m];
    __syncthreads();
    {
      const float2* K = Ksh[0][warp];
#pragma unroll
      for (int m=0;m<AMPS;m++){
        int p = (m<<8) + tid;
        float2 acc = cmul(K[0], bufA[p]);
#pragma unroll
        for (int d=1; d<8; d++){
          float2 w0 = bufA[p ^ (d<<5)];
          float2 kd = K[d];
          acc.x += kd.x*w0.x - kd.y*w0.y;
          acc.y += kd.x*w0.y + kd.y*w0.x;
        }
        v[m] = acc;
      }
    }
    shflC(v, Ug[3], 4, lane);
    shflC(v, Ug[4], 3, lane);
    shflC(v, Ug[5], 2, lane);
    shflC(v, Ug[6], 1, lane);
    shflC(v, Ug[7], 0, lane);
    regC(v, Ug[8], 2);
    regC(v, Ug[9], 1);

    // ======== section 2: chain gather fused with layer-2 cross gate ========
#pragma unroll
    for (int m=0;m<AMPS;m++) bufB[(m<<8) + tid] = v[m];
    __syncthreads();
    {
      const float2* K = Ksh[1][warp];
#pragma unroll
      for (int m=0;m<AMPS;m++){
        int p = posJ[m];
        float2 acc = cmul(K[0], bufB[p]);
#pragma unroll
        for (int d=1; d<8; d++){
          float2 w0 = bufB[p ^ ((d<<5) ^ (d<<4))];
          float2 kd = K[d];
          acc.x += kd.x*w0.x - kd.y*w0.y;
          acc.y += kd.x*w0.y + kd.y*w0.x;
        }
        v[m] = acc;
      }
    }
    shflC(v, Ug[13], 4, lane);
    shflC(v, Ug[14], 3, lane);
    shflC(v, Ug[15], 2, lane);
    shflC(v, Ug[16], 1, lane);
    shflC(v, Ug[17], 0, lane);
    regC(v, Ug[18], 2);
    regC(v, Ug[19], 1);

    // ======== section 3: chain gather fused with final-RY cross gate ========
#pragma unroll
    for (int m=0;m<AMPS;m++) bufA[(m<<8) + tid] = v[m];
    __syncthreads();
    {
      const float2* K = K3sh[warp];
#pragma unroll
      for (int m=0;m<AMPS;m++){
        int p = posJ[m];
        float accx = K[0].x * bufA[p].x;
        float accy = K[0].x * bufA[p].y;
#pragma unroll
        for (int d=1; d<8; d++){
          float2 w0 = bufA[p ^ ((d<<5) ^ (d<<4))];
          float kd = K[d].x;
          accx += kd*w0.x;
          accy += kd*w0.y;
        }
        v[m] = make_float2(accx, accy);
      }
    }
    shflR(v, fcs[3], fss[3], 4, lane);
    shflR(v, fcs[4], fss[4], 3, lane);
    shflR(v, fcs[5], fss[5], 2, lane);
    shflR(v, fcs[6], fss[6], 1, lane);
    shflR(v, fcs[7], fss[7], 0, lane);
    regR(v, fcs[8], fss[8], 2);
    regR(v, fcs[9], fss[9], 1);

    // ======== measurement ========
    float S=0.f, SbH=0.f, SbL=0.f;
#pragma unroll
    for (int m=0;m<AMPS;m++){
      float pm = v[m].x*v[m].x + v[m].y*v[m].y;
      S += pm;
      if (m & 2) SbH += pm;   // wire 8
      if (m & 1) SbL += pm;   // wire 9
    }
    // plain lane sums for wires 8,9
#pragma unroll
    for (int off=16; off>0; off>>=1){
      SbH += __shfl_xor_sync(0xffffffffu, SbH, off);
      SbL += __shfl_xor_sync(0xffffffffu, SbL, off);
    }
    // Walsh-Hadamard on S: lane j ends with sum_l (-1)^{popc(j&l)} S_l
#pragma unroll
    for (int q=16; q>0; q>>=1){
      float t = __shfl_xor_sync(0xffffffffu, S, q);
      S = ((lane & q) ? (t - S) : (S + t));
    }
    if (lane == 0){
      zred[warp][0] = (warp&4) ? -S : S;
      zred[warp][1] = (warp&2) ? -S : S;
      zred[warp][2] = (warp&1) ? -S : S;
      zred[warp][8] = S - 2.f*SbH;
      zred[warp][9] = S - 2.f*SbL;
    } else if (lane == 16) zred[warp][3] = S;
    else if (lane == 8)  zred[warp][4] = S;
    else if (lane == 4)  zred[warp][5] = S;
    else if (lane == 2)  zred[warp][6] = S;
    else if (lane == 1)  zred[warp][7] = S;
    __syncthreads();

    if (tid < NQ){
      float hn = zred[0][tid] + zred[1][tid] + zred[2][tid] + zred[3][tid]
               + zred[4][tid] + zred[5][tid] + zred[6][tid] + zred[7][tid];
      int bi = (b*SQ + s)*NQ + tid;
      out[bi] = pC*hn + Dsh[tid]*pA;
      if (s+1 < SQ){
        float s_, c_;
        __sincosf(0.5f*hn, &s_, &c_);
        chs[tid] = c_; shs[tid] = s_;
        whs[tid] = nD * (0.5f*PI_F);
        __sincosf(0.5f*nA*nD, &s_, &c_);
        fcs[tid] = c_; fss[tid] = s_;
        pA = nA; pC = nC;
      }
    }
    __syncthreads();
  }
}

// ---------------------------------------------------------------------------
extern "C" void kernel_launch(void* const* d_in, const int* in_sizes, int n_in,
                              void* d_out, int out_size)
{
  const float* angles  = (const float*)d_in[0];
  const float* W_x     = (const float*)d_in[1];
  const float* W_dt    = (const float*)d_in[2];
  const float* b_dt    = (const float*)d_in[3];
  const float* poly    = (const float*)d_in[4];
  const float* cparams = (const float*)d_in[5];
  const float* D       = (const float*)d_in[6];
  float* out = (float*)d_out;

  prep_kernel<<<(BQ*SQ + 255)/256, 256>>>(angles, W_x, W_dt, b_dt);
  qmamba_main<<<BQ, TPB>>>(angles, poly, cparams, D, out);
}

// round 7
// speedup vs baseline: 1.7189x; 1.0189x over previous
#include <cuda_runtime.h>

#define BQ 128
#define SQ 512
#define NQ 10
#define NST 1024
#define TPB 256
#define AMPS 4
#define PI_F 3.14159265358979f

typedef unsigned long long u64;

// scratch (no allocations allowed)
__device__ float g_dta[BQ*SQ*NQ];
__device__ float g_C[BQ*SQ*NQ];

__device__ __forceinline__ float2 cmul(float2 a, float2 b){
  return make_float2(a.x*b.x - a.y*b.y, a.x*b.y + a.y*b.x);
}

// ---- packed f32x2 helpers (Blackwell FFMA2 via PTX); carrier = u64 ----------
__device__ __forceinline__ u64 pk2(float x, float y){
  u64 d; asm("mov.b64 %0,{%1,%2};" : "=l"(d) : "f"(x), "f"(y)); return d;
}
__device__ __forceinline__ float2 up2(u64 d){
  float2 f; asm("mov.b64 {%0,%1},%2;" : "=f"(f.x), "=f"(f.y) : "l"(d)); return f;
}
__device__ __forceinline__ u64 fma2d(u64 a, u64 b, u64 c){
  u64 r; asm("fma.rn.f32x2 %0,%1,%2,%3;" : "=l"(r) : "l"(a), "l"(b), "l"(c)); return r;
}
__device__ __forceinline__ u64 mul2d(u64 a, u64 b){
  u64 r; asm("mul.rn.f32x2 %0,%1,%2;" : "=l"(r) : "l"(a), "l"(b)); return r;
}
// (P,Q) dual-accumulator -> packed complex: re = P.lo - Q.hi, im = P.hi + Q.lo
__device__ __forceinline__ u64 fixPQ(u64 P, u64 Q){
  float2 p = up2(P), q = up2(Q);
  return pk2(p.x - q.y, p.y + q.x);
}

// verified QSVT gather map: wrap CNOT(9,0) then chain, reverse-applied
__device__ __forceinline__ int gmap(int a){
  int v = a;
  v ^= (v & 1) << 9;
#pragma unroll
  for (int i = 8; i >= 0; --i) v ^= ((v >> (9-i)) & 1) << (8-i);
  return v;
}

// ---------------------------------------------------------------------------
__global__ void prep_kernel(const float* __restrict__ angles,
                            const float* __restrict__ W_x,
                            const float* __restrict__ W_dt,
                            const float* __restrict__ b_dt)
{
  int idx = blockIdx.x*blockDim.x + threadIdx.x;
  if (idx >= BQ*SQ) return;
  float a[NQ];
#pragma unroll
  for (int n=0;n<NQ;n++) a[n] = angles[idx*NQ + n];
  float dtr[5];
#pragma unroll
  for (int r=0;r<5;r++){
    float s = 0.f;
#pragma unroll
    for (int n=0;n<NQ;n++) s += a[n]*W_x[r*NQ+n];
    dtr[r]=s;
  }
#pragma unroll
  for (int k=0;k<NQ;k++){
    float s=0.f;
#pragma unroll
    for (int n=0;n<NQ;n++) s += a[n]*W_x[(15+k)*NQ+n];
    g_C[idx*NQ+k]=s;
  }
#pragma unroll
  for (int n=0;n<NQ;n++){
    float s = b_dt[n];
#pragma unroll
    for (int r=0;r<5;r++) s += dtr[r]*W_dt[n*5+r];
    float sp = fmaxf(s, 0.f) + log1pf(expf(-fabsf(s)));
    g_dta[idx*NQ+n] = tanhf(sp)*PI_F;
  }
}

// complex shuffle gate on lane bit q, packed state, dual-accumulator
__device__ __forceinline__ void shflCp(u64* v, const u64* Cq, int q){
  u64 csx=Cq[0], csy=Cq[1], cpx=Cq[2], cpy=Cq[3];
#pragma unroll
  for (int m=0;m<AMPS;m++){
    u64 p = __shfl_xor_sync(0xffffffffu, v[m], 1<<q);
    u64 P = fma2d(cpx, p, mul2d(csx, v[m]));
    u64 Q = fma2d(cpy, p, mul2d(csy, v[m]));
    v[m] = fixPQ(P, Q);
  }
}

// real (RY) shuffle gate on lane bit q, packed state
__device__ __forceinline__ void shflRp(u64* v, float c, float s, int q, int lane){
  float sp = ((lane >> q) & 1) ? s : -s;
  u64 c2 = pk2(c, c), sp2 = pk2(sp, sp);
#pragma unroll
  for (int m=0;m<AMPS;m++){
    u64 p = __shfl_xor_sync(0xffffffffu, v[m], 1<<q);
    v[m] = fma2d(sp2, p, mul2d(c2, v[m]));
  }
}

// complex register gate on m-bit bm, packed state, dual-accumulator
__device__ __forceinline__ void regCp(u64* v, const u64* G, int bm){
  u64 g0x=G[0],g0y=G[1],g1x=G[2],g1y=G[3],g2x=G[4],g2y=G[5],g3x=G[6],g3y=G[7];
#pragma unroll
  for (int m=0;m<AMPS;m++){
    if (m & bm) continue;
    int mh = m | bm;
    u64 lo = v[m], hi = v[mh];
    u64 P = fma2d(g1x, hi, mul2d(g0x, lo));
    u64 Q = fma2d(g1y, hi, mul2d(g0y, lo));
    v[m]  = fixPQ(P, Q);
    P = fma2d(g3x, hi, mul2d(g2x, lo));
    Q = fma2d(g3y, hi, mul2d(g2y, lo));
    v[mh] = fixPQ(P, Q);
  }
}

// real (RY) register gate on m-bit bm, packed state
__device__ __forceinline__ void regRp(u64* v, float c, float s, int bm){
  u64 c2 = pk2(c,c), s2 = pk2(s,s), ns2 = pk2(-s,-s);
#pragma unroll
  for (int m=0;m<AMPS;m++){
    if (m & bm) continue;
    int mh = m | bm;
    u64 lo = v[m], hi = v[mh];
    v[m]  = fma2d(ns2, hi, mul2d(c2, lo));
    v[mh] = fma2d(c2, hi, mul2d(s2, lo));
  }
}

// ---------------------------------------------------------------------------
// 256 threads, 4 amps/thread, state packed (re,im) per 64-bit register.
// amp a = tid*4+m. bits: [1:0]=m (wires 8,9), [6:2]=lane (wires 3..7),
// [9:7]=warp (wires 0,1,2). pos(a) = (a&3)*256 + (a>>2).
// ---------------------------------------------------------------------------
__global__ __launch_bounds__(TPB, 1) void qmamba_main(
    const float* __restrict__ angles,
    const float* __restrict__ poly,
    const float* __restrict__ cparams,
    const float* __restrict__ Dg,
    float* __restrict__ out)
{
  __shared__ u64 bufA[NST], bufB[NST];
  __shared__ float2 Ug[20][4];
  __shared__ u64 Kp[2][8][8][2];   // static cross coeffs, packed (kx2, ky2)
  __shared__ u64 K3p[8][8];        // per-step RY cross coeffs, packed (k,k)
  __shared__ u64 Ugp[20][2][4];    // per-gate per-bt packed shuffle coeffs
  __shared__ u64 Urp[4][8];        // packed reg-gate coeffs (gates 8,9,18,19)
  __shared__ float Slo[32], Shi[32], Alo[32], Ahi[32];
  __shared__ float chs[NQ], shs[NQ], whs[NQ], fcs[NQ], fss[NQ];
  __shared__ float pcs[4], Dsh[NQ];
  __shared__ float zred[8][NQ];

  const int tid = threadIdx.x;
  const int lane = tid & 31;
  const int warp = tid >> 5;
  const int b = blockIdx.x;

  // ---- setup ---------------------------------------------------------------
  if (tid < 20) {
    int layer = tid/10, wire = tid%10;
    int k = (layer*NQ + wire)*3;
    float al = cparams[k], be = cparams[k+1], ga = cparams[k+2];
    float sa, ca, sb, cb, sg, cg;
    sincosf(0.5f*al, &sa, &ca);
    sincosf(0.5f*be, &sb, &cb);
    sincosf(0.5f*ga, &sg, &cg);
    float2 m00 = make_float2( cb*ca,  sb*sa);
    float2 m01 = make_float2(-sb*ca, -cb*sa);
    float2 m10 = make_float2( sb*ca, -cb*sa);
    float2 m11 = make_float2( cb*ca, -sb*sa);
    float2 e0 = make_float2(cg, -sg);
    float2 e1 = make_float2(cg,  sg);
    Ug[tid][0] = cmul(e0, m00);
    Ug[tid][1] = cmul(e0, m01);
    Ug[tid][2] = cmul(e1, m10);
    Ug[tid][3] = cmul(e1, m11);
  }
  if (tid < 4) pcs[tid] = poly[tid];
  float pA = 0.f, pC = 0.f;
  if (tid < NQ) {
    Dsh[tid] = Dg[tid];
    int bi = b*SQ*NQ + tid;
    pA = angles[bi]; pC = g_C[bi];
    float dta = g_dta[bi];
    chs[tid] = 1.f; shs[tid] = 0.f;     // h=0 at step 0
    whs[tid] = dta * (0.5f*PI_F);
    float s_, c_;
    __sincosf(0.5f*pA*dta, &s_, &c_);
    fcs[tid] = c_; fss[tid] = s_;
  }
  __syncthreads();

  // static packed cross coefficients Kp[L][w][d][part]
  {
    int L = tid >> 7;
    int w = (tid >> 4) & 7;
    int d = (tid >> 1) & 7;
    int part = tid & 1;
    int rA=(w>>2)&1, rB=(w>>1)&1, rC=w&1;
    int dA=(d>>2)&1, dB=(d>>1)&1, dC=d&1;
    float2 k = cmul(Ug[L*10+0][rA*2 + (rA^dA)],
               cmul(Ug[L*10+1][rB*2 + (rB^dB)],
                    Ug[L*10+2][rC*2 + (rC^dC)]));
    float val = part ? k.y : k.x;
    Kp[L][w][d][part] = pk2(val, val);
  }
  // static packed shuffle-gate coefficients Ugp[g][bt][c]
  if (tid < 160) {
    int g = tid >> 3;
    int bt = (tid >> 2) & 1;
    int c = tid & 3;
    float2 cs = bt ? Ug[g][3] : Ug[g][0];
    float2 cp = bt ? Ug[g][2] : Ug[g][1];
    float val = (c==0) ? cs.x : (c==1) ? cs.y : (c==2) ? cp.x : cp.y;
    Ugp[g][bt][c] = pk2(val, val);
  }
  // static packed reg-gate coefficients Urp for gates 8,9,18,19
  if (tid < 32) {
    int gi = tid >> 3;
    int gate = (gi < 2) ? (8 + gi) : (16 + gi);   // 8,9,18,19
    int c = (tid >> 1) & 3;
    int part = tid & 1;
    float2 gv = Ug[gate][c];
    float val = part ? gv.y : gv.x;
    Urp[gi][2*c+part] = pk2(val, val);
  }

  // per-thread static: QSVT gather powers + fused-gather positions
  int rT1[AMPS], rT2[AMPS], rT3[AMPS], rT4[AMPS], posJ[AMPS];
#pragma unroll
  for (int m=0;m<AMPS;m++){
    int a = tid*AMPS + m;
    rT1[m] = gmap(a);
    rT2[m] = gmap(rT1[m]);
    rT3[m] = gmap(rT2[m]);
    rT4[m] = gmap(rT3[m]);
    int j0 = a ^ (a >> 1);
    posJ[m] = ((j0 & 3) << 8) | (j0 >> 2);
  }
  __syncthreads();

  u64 v[AMPS];

  // ---- sequential scan -----------------------------------------------------
#pragma unroll 1
  for (int s = 0; s < SQ; ++s) {
    // prefetch next-step per-wire inputs
    float nA=0.f, nD=0.f, nC=0.f;
    if (tid < NQ && s+1 < SQ) {
      int bn = (b*SQ + s + 1)*NQ + tid;
      nA = angles[bn]; nD = g_dta[bn]; nC = g_C[bn];
    }
    // per-step split tables over 5-bit halves
    if (tid < 64) {
      int j = tid & 31;
      bool hi = tid >= 32;
      float sm = 0.f, am = 1.f;
#pragma unroll
      for (int q=0;q<5;q++){
        int w = hi ? (4-q) : (9-q);
        int bit = (j>>q)&1;
        sm += bit ? whs[w] : -whs[w];
        am *= bit ? shs[w] : chs[w];
      }
      if (hi){ Shi[j]=sm; Ahi[j]=am; } else { Slo[j]=sm; Alo[j]=am; }
    }
    // per-step final-RY packed cross coefficients (wires 0,1,2)
    if (tid >= 64 && tid < 128) {
      int t = tid - 64;
      int w = t >> 3, d = t & 7;
      float f0 = (d&4) ? ((w&4) ? fss[0] : -fss[0]) : fcs[0];
      float f1 = (d&2) ? ((w&2) ? fss[1] : -fss[1]) : fcs[1];
      float f2 = (d&1) ? ((w&1) ? fss[2] : -fss[2]) : fcs[2];
      float k3 = f0*f1*f2;
      K3p[w][d] = pk2(k3, k3);
    }
    __syncthreads();

    // init in registers: product state advanced through entire QSVT block
    {
      float p0=pcs[0], p1=pcs[1], p2=pcs[2], p3=pcs[3];
#pragma unroll
      for (int m=0;m<AMPS;m++){
        float phi = p3*(Shi[rT1[m]>>5] + Slo[rT1[m]&31])
                  + p2*(Shi[rT2[m]>>5] + Slo[rT2[m]&31])
                  + p1*(Shi[rT3[m]>>5] + Slo[rT3[m]&31])
                  + p0*(Shi[rT4[m]>>5] + Slo[rT4[m]&31]);
        float am = Ahi[rT4[m]>>5] * Alo[rT4[m]&31];
        float sp, cp; __sincosf(phi, &sp, &cp);
        v[m] = pk2(am*cp, am*sp);
      }
    }

    // ======== section 1: layer-1 gates ========
#pragma unroll
    for (int m=0;m<AMPS;m++) bufA[(m<<8) + tid] = v[m];
    __syncthreads();
    {
      u64 kx[8], ky[8];
#pragma unroll
      for (int d=0; d<8; d++){ kx[d] = Kp[0][warp][d][0]; ky[d] = Kp[0][warp][d][1]; }
#pragma unroll
      for (int m=0;m<AMPS;m++){
        int p = (m<<8) + tid;
        u64 w0 = bufA[p];
        u64 P = mul2d(kx[0], w0);
        u64 Q = mul2d(ky[0], w0);
#pragma unroll
        for (int d=1; d<8; d++){
          u64 wd = bufA[p ^ (d<<5)];
          P = fma2d(kx[d], wd, P);
          Q = fma2d(ky[d], wd, Q);
        }
        v[m] = fixPQ(P, Q);
      }
    }
    shflCp(v, Ugp[3][(lane>>4)&1], 4);
    shflCp(v, Ugp[4][(lane>>3)&1], 3);
    shflCp(v, Ugp[5][(lane>>2)&1], 2);
    shflCp(v, Ugp[6][(lane>>1)&1], 1);
    shflCp(v, Ugp[7][lane&1], 0);
    regCp(v, Urp[0], 2);
    regCp(v, Urp[1], 1);

    // ======== section 2: chain gather fused with layer-2 cross gate ========
#pragma unroll
    for (int m=0;m<AMPS;m++) bufB[(m<<8) + tid] = v[m];
    __syncthreads();
    {
      u64 kx[8], ky[8];
#pragma unroll
      for (int d=0; d<8; d++){ kx[d] = Kp[1][warp][d][0]; ky[d] = Kp[1][warp][d][1]; }
#pragma unroll
      for (int m=0;m<AMPS;m++){
        int p = posJ[m];
        u64 w0 = bufB[p];
        u64 P = mul2d(kx[0], w0);
        u64 Q = mul2d(ky[0], w0);
#pragma unroll
        for (int d=1; d<8; d++){
          u64 wd = bufB[p ^ ((d<<5) ^ (d<<4))];
          P = fma2d(kx[d], wd, P);
          Q = fma2d(ky[d], wd, Q);
        }
        v[m] = fixPQ(P, Q);
      }
    }
    shflCp(v, Ugp[13][(lane>>4)&1], 4);
    shflCp(v, Ugp[14][(lane>>3)&1], 3);
    shflCp(v, Ugp[15][(lane>>2)&1], 2);
    shflCp(v, Ugp[16][(lane>>1)&1], 1);
    shflCp(v, Ugp[17][lane&1], 0);
    regCp(v, Urp[2], 2);
    regCp(v, Urp[3], 1);

    // ======== section 3: chain gather fused with final-RY cross gate ========
#pragma unroll
    for (int m=0;m<AMPS;m++) bufA[(m<<8) + tid] = v[m];
    __syncthreads();
    {
      u64 k3[8];
#pragma unroll
      for (int d=0; d<8; d++) k3[d] = K3p[warp][d];
#pragma unroll
      for (int m=0;m<AMPS;m++){
        int p = posJ[m];
        u64 acc = mul2d(k3[0], bufA[p]);
#pragma unroll
        for (int d=1; d<8; d++){
          u64 wd = bufA[p ^ ((d<<5) ^ (d<<4))];
          acc = fma2d(k3[d], wd, acc);
        }
        v[m] = acc;
      }
    }
    shflRp(v, fcs[3], fss[3], 4, lane);
    shflRp(v, fcs[4], fss[4], 3, lane);
    shflRp(v, fcs[5], fss[5], 2, lane);
    shflRp(v, fcs[6], fss[6], 1, lane);
    shflRp(v, fcs[7], fss[7], 0, lane);
    regRp(v, fcs[8], fss[8], 2);
    regRp(v, fcs[9], fss[9], 1);

    // ======== measurement ========
    float S=0.f, SbH=0.f, SbL=0.f;
#pragma unroll
    for (int m=0;m<AMPS;m++){
      float2 f = up2(v[m]);
      float pm = f.x*f.x + f.y*f.y;
      S += pm;
      if (m & 2) SbH += pm;   // wire 8
      if (m & 1) SbL += pm;   // wire 9
    }
#pragma unroll
    for (int off=16; off>0; off>>=1){
      SbH += __shfl_xor_sync(0xffffffffu, SbH, off);
      SbL += __shfl_xor_sync(0xffffffffu, SbL, off);
    }
    // Walsh-Hadamard on S: lane j ends with sum_l (-1)^{popc(j&l)} S_l
#pragma unroll
    for (int q=16; q>0; q>>=1){
      float t = __shfl_xor_sync(0xffffffffu, S, q);
      S = ((lane & q) ? (t - S) : (S + t));
    }
    if (lane == 0){
      zred[warp][0] = (warp&4) ? -S : S;
      zred[warp][1] = (warp&2) ? -S : S;
      zred[warp][2] = (warp&1) ? -S : S;
      zred[warp][8] = S - 2.f*SbH;
      zred[warp][9] = S - 2.f*SbL;
    } else if (lane == 16) zred[warp][3] = S;
    else if (lane == 8)  zred[warp][4] = S;
    else if (lane == 4)  zred[warp][5] = S;
    else if (lane == 2)  zred[warp][6] = S;
    else if (lane == 1)  zred[warp][7] = S;
    __syncthreads();

    if (tid < NQ){
      float hn = zred[0][tid] + zred[1][tid] + zred[2][tid] + zred[3][tid]
               + zred[4][tid] + zred[5][tid] + zred[6][tid] + zred[7][tid];
      int bi = (b*SQ + s)*NQ + tid;
      out[bi] = pC*hn + Dsh[tid]*pA;
      if (s+1 < SQ){
        float s_, c_;
        __sincosf(0.5f*hn, &s_, &c_);
        chs[tid] = c_; shs[tid] = s_;
        whs[tid] = nD * (0.5f*PI_F);
        __sincosf(0.5f*nA*nD, &s_, &c_);
        fcs[tid] = c_; fss[tid] = s_;
        pA = nA; pC = nC;
      }
    }
    __syncthreads();
  }
}

// ---------------------------------------------------------------------------
extern "C" void kernel_launch(void* const* d_in, const int* in_sizes, int n_in,
                              void* d_out, int out_size)
{
  const float* angles  = (const float*)d_in[0];
  const float* W_x     = (const float*)d_in[1];
  const float* W_dt    = (const float*)d_in[2];
  const float* b_dt    = (const float*)d_in[3];
  const float* poly    = (const float*)d_in[4];
  const float* cparams = (const float*)d_in[5];
  const float* D       = (const float*)d_in[6];
  float* out = (float*)d_out;

  prep_kernel<<<(BQ*SQ + 255)/256, 256>>>(angles, W_x, W_dt, b_dt);
  qmamba_main<<<BQ, TPB>>>(angles, poly, cparams, D, out);
}